// round 2
// baseline (speedup 1.0000x reference)
#include <cuda_runtime.h>
#include <math.h>

#define N_NODES 10000
#define DIM     1024
#define NREL    8
#define NEDGE   80000
#define K1      (DIM + NREL * DIM)   /* 9216 */
#define K2      (2 * DIM)            /* 2048 */

#define BM 128
#define BN 128
#define BK 16
#define APAD 4

/* Scratch (device globals: no allocation allowed) */
__device__ float g_agg[(size_t)N_NODES * NREL * DIM];
__device__ float g_cnt[N_NODES * NREL];
__device__ float g_U[(size_t)N_NODES * DIM];
__device__ int   g_is64;   /* 1 if edge tensors are int64, 0 if int32 */

/* ------------------------------------------------------------------ */
__global__ void detect_kernel(const int* __restrict__ ei) {
    /* int64 non-negative < 2^31: every odd 32-bit word is 0.
       int32 node ids: odd words are random in [0,10000). */
    if (threadIdx.x == 0 && blockIdx.x == 0) {
        int allzero = 1;
        for (int i = 1; i < 4096; i += 2)
            if (ei[i] != 0) { allzero = 0; break; }
        g_is64 = allzero;
    }
}

__global__ void zero_scratch_kernel() {
    size_t idx    = (size_t)blockIdx.x * blockDim.x + threadIdx.x;
    size_t stride = (size_t)gridDim.x * blockDim.x;
    float4* agg4 = reinterpret_cast<float4*>(g_agg);
    const size_t nagg4 = (size_t)N_NODES * NREL * DIM / 4;
    for (size_t i = idx; i < nagg4; i += stride)
        agg4[i] = make_float4(0.f, 0.f, 0.f, 0.f);
    float4* cnt4 = reinterpret_cast<float4*>(g_cnt);
    const size_t ncnt4 = (size_t)N_NODES * NREL / 4;
    for (size_t i = idx; i < ncnt4; i += stride)
        cnt4[i] = make_float4(0.f, 0.f, 0.f, 0.f);
}

/* One block per edge: scatter x[src] into agg[dst, rel] and bump count. */
__global__ __launch_bounds__(256)
void scatter_kernel(const float* __restrict__ x,
                    const void* __restrict__ edge_index,
                    const void* __restrict__ edge_type) {
    int e = blockIdx.x;
    int src, dst, r;
    if (g_is64) {
        const long long* ei = (const long long*)edge_index;
        const long long* et = (const long long*)edge_type;
        src = (int)ei[e]; dst = (int)ei[NEDGE + e]; r = (int)et[e];
    } else {
        const int* ei = (const int*)edge_index;
        const int* et = (const int*)edge_type;
        src = ei[e]; dst = ei[NEDGE + e]; r = et[e];
    }
    const float4* xs  = reinterpret_cast<const float4*>(x + (size_t)src * DIM);
    float* out = g_agg + ((size_t)dst * NREL + r) * DIM;
    int t = threadIdx.x;            /* 256 threads, 4 floats each */
    float4 v = xs[t];
    atomicAdd(out + t * 4 + 0, v.x);
    atomicAdd(out + t * 4 + 1, v.y);
    atomicAdd(out + t * 4 + 2, v.z);
    atomicAdd(out + t * 4 + 3, v.w);
    if (t == 0)
        atomicAdd(&g_cnt[dst * NREL + r], 1.0f);
}

/* ------------------------------------------------------------------ */
/* GEMM1: U = [x | mean] @ [root ; weight] + bias (mean-normalization
   fused into the A loader).                                           */
__global__ __launch_bounds__(256)
void gemm1_kernel(const float* __restrict__ x,
                  const float* __restrict__ root,
                  const float* __restrict__ weight,
                  const float* __restrict__ bias) {
    __shared__ float As[BK][BM + APAD];
    __shared__ float Bs[BK][BN];

    const int tid  = threadIdx.x;
    const int m0   = blockIdx.y * BM;
    const int n0   = blockIdx.x * BN;
    const int trow = tid >> 4;
    const int tcol = tid & 15;

    float acc[8][8];
#pragma unroll
    for (int i = 0; i < 8; i++)
#pragma unroll
        for (int j = 0; j < 8; j++) acc[i][j] = 0.f;

    for (int k0 = 0; k0 < K1; k0 += BK) {
#pragma unroll
        for (int it = 0; it < 2; it++) {
            int idx  = tid + it * 256;
            int row  = idx >> 2;
            int c4   = (idx & 3) << 2;
            int grow = m0 + row;
            float4 v = make_float4(0.f, 0.f, 0.f, 0.f);
            if (grow < N_NODES) {
                if (k0 < DIM) {
                    v = *reinterpret_cast<const float4*>(
                        x + (size_t)grow * DIM + k0 + c4);
                } else {
                    int kk = k0 - DIM;
                    int r  = kk >> 10;
                    float c = g_cnt[grow * NREL + r];
                    float s = 1.0f / fmaxf(c, 1.0f);
                    float4 t = *reinterpret_cast<const float4*>(
                        g_agg + (size_t)grow * (NREL * DIM) + kk + c4);
                    v.x = t.x * s; v.y = t.y * s; v.z = t.z * s; v.w = t.w * s;
                }
            }
            As[c4 + 0][row] = v.x;
            As[c4 + 1][row] = v.y;
            As[c4 + 2][row] = v.z;
            As[c4 + 3][row] = v.w;
        }
        const float* Bp = (k0 < DIM) ? (root + (size_t)k0 * DIM)
                                     : (weight + (size_t)(k0 - DIM) * DIM);
#pragma unroll
        for (int it = 0; it < 2; it++) {
            int idx = tid + it * 256;
            int row = idx >> 5;
            int c4  = (idx & 31) << 2;
            float4 v = *reinterpret_cast<const float4*>(Bp + (size_t)row * DIM + n0 + c4);
            *reinterpret_cast<float4*>(&Bs[row][c4]) = v;
        }
        __syncthreads();

#pragma unroll
        for (int k = 0; k < BK; k++) {
            float4 a0 = *reinterpret_cast<const float4*>(&As[k][trow * 8]);
            float4 a1 = *reinterpret_cast<const float4*>(&As[k][trow * 8 + 4]);
            float4 b0 = *reinterpret_cast<const float4*>(&Bs[k][tcol * 8]);
            float4 b1 = *reinterpret_cast<const float4*>(&Bs[k][tcol * 8 + 4]);
            float a[8] = {a0.x, a0.y, a0.z, a0.w, a1.x, a1.y, a1.z, a1.w};
            float b[8] = {b0.x, b0.y, b0.z, b0.w, b1.x, b1.y, b1.z, b1.w};
#pragma unroll
            for (int i = 0; i < 8; i++)
#pragma unroll
                for (int j = 0; j < 8; j++)
                    acc[i][j] = fmaf(a[i], b[j], acc[i][j]);
        }
        __syncthreads();
    }

#pragma unroll
    for (int i = 0; i < 8; i++) {
        int grow = m0 + trow * 8 + i;
        if (grow >= N_NODES) continue;
        int gn = n0 + tcol * 8;
        float4 bia0 = *reinterpret_cast<const float4*>(bias + gn);
        float4 bia1 = *reinterpret_cast<const float4*>(bias + gn + 4);
        float4 o0 = make_float4(acc[i][0] + bia0.x, acc[i][1] + bia0.y,
                                acc[i][2] + bia0.z, acc[i][3] + bia0.w);
        float4 o1 = make_float4(acc[i][4] + bia1.x, acc[i][5] + bia1.y,
                                acc[i][6] + bia1.z, acc[i][7] + bia1.w);
        *reinterpret_cast<float4*>(g_U + (size_t)grow * DIM + gn)     = o0;
        *reinterpret_cast<float4*>(g_U + (size_t)grow * DIM + gn + 4) = o1;
    }
}

/* ------------------------------------------------------------------ */
/* GEMM2: z = [U | x] @ w_gate + b_gate, fused h = tanh(u)z + x(1-z). */
__global__ __launch_bounds__(256)
void gemm2_kernel(const float* __restrict__ x,
                  const float* __restrict__ w_gate,
                  const float* __restrict__ b_gate,
                  float* __restrict__ out) {
    __shared__ float As[BK][BM + APAD];
    __shared__ float Bs[BK][BN];

    const int tid  = threadIdx.x;
    const int m0   = blockIdx.y * BM;
    const int n0   = blockIdx.x * BN;
    const int trow = tid >> 4;
    const int tcol = tid & 15;

    float acc[8][8];
#pragma unroll
    for (int i = 0; i < 8; i++)
#pragma unroll
        for (int j = 0; j < 8; j++) acc[i][j] = 0.f;

    for (int k0 = 0; k0 < K2; k0 += BK) {
#pragma unroll
        for (int it = 0; it < 2; it++) {
            int idx  = tid + it * 256;
            int row  = idx >> 2;
            int c4   = (idx & 3) << 2;
            int grow = m0 + row;
            float4 v = make_float4(0.f, 0.f, 0.f, 0.f);
            if (grow < N_NODES) {
                const float* Ap = (k0 < DIM)
                    ? (g_U + (size_t)grow * DIM + k0)
                    : (x + (size_t)grow * DIM + (k0 - DIM));
                v = *reinterpret_cast<const float4*>(Ap + c4);
            }
            As[c4 + 0][row] = v.x;
            As[c4 + 1][row] = v.y;
            As[c4 + 2][row] = v.z;
            As[c4 + 3][row] = v.w;
        }
        const float* Bp = w_gate + (size_t)k0 * DIM;
#pragma unroll
        for (int it = 0; it < 2; it++) {
            int idx = tid + it * 256;
            int row = idx >> 5;
            int c4  = (idx & 31) << 2;
            float4 v = *reinterpret_cast<const float4*>(Bp + (size_t)row * DIM + n0 + c4);
            *reinterpret_cast<float4*>(&Bs[row][c4]) = v;
        }
        __syncthreads();

#pragma unroll
        for (int k = 0; k < BK; k++) {
            float4 a0 = *reinterpret_cast<const float4*>(&As[k][trow * 8]);
            float4 a1 = *reinterpret_cast<const float4*>(&As[k][trow * 8 + 4]);
            float4 b0 = *reinterpret_cast<const float4*>(&Bs[k][tcol * 8]);
            float4 b1 = *reinterpret_cast<const float4*>(&Bs[k][tcol * 8 + 4]);
            float a[8] = {a0.x, a0.y, a0.z, a0.w, a1.x, a1.y, a1.z, a1.w};
            float b[8] = {b0.x, b0.y, b0.z, b0.w, b1.x, b1.y, b1.z, b1.w};
#pragma unroll
            for (int i = 0; i < 8; i++)
#pragma unroll
                for (int j = 0; j < 8; j++)
                    acc[i][j] = fmaf(a[i], b[j], acc[i][j]);
        }
        __syncthreads();
    }

#pragma unroll
    for (int i = 0; i < 8; i++) {
        int grow = m0 + trow * 8 + i;
        if (grow >= N_NODES) continue;
        int gn = n0 + tcol * 8;
        float4 bg0 = *reinterpret_cast<const float4*>(b_gate + gn);
        float4 bg1 = *reinterpret_cast<const float4*>(b_gate + gn + 4);
        float4 u0  = *reinterpret_cast<const float4*>(g_U + (size_t)grow * DIM + gn);
        float4 u1  = *reinterpret_cast<const float4*>(g_U + (size_t)grow * DIM + gn + 4);
        float4 x0  = *reinterpret_cast<const float4*>(x + (size_t)grow * DIM + gn);
        float4 x1  = *reinterpret_cast<const float4*>(x + (size_t)grow * DIM + gn + 4);
        float zz[8] = {acc[i][0] + bg0.x, acc[i][1] + bg0.y,
                       acc[i][2] + bg0.z, acc[i][3] + bg0.w,
                       acc[i][4] + bg1.x, acc[i][5] + bg1.y,
                       acc[i][6] + bg1.z, acc[i][7] + bg1.w};
        float uu[8] = {u0.x, u0.y, u0.z, u0.w, u1.x, u1.y, u1.z, u1.w};
        float xx[8] = {x0.x, x0.y, x0.z, x0.w, x1.x, x1.y, x1.z, x1.w};
        float hh[8];
#pragma unroll
        for (int j = 0; j < 8; j++)
            hh[j] = tanhf(uu[j]) * zz[j] + xx[j] * (1.0f - zz[j]);
        float4 o0 = make_float4(hh[0], hh[1], hh[2], hh[3]);
        float4 o1 = make_float4(hh[4], hh[5], hh[6], hh[7]);
        *reinterpret_cast<float4*>(out + (size_t)grow * DIM + gn)     = o0;
        *reinterpret_cast<float4*>(out + (size_t)grow * DIM + gn + 4) = o1;
    }
}

/* ------------------------------------------------------------------ */
extern "C" void kernel_launch(void* const* d_in, const int* in_sizes, int n_in,
                              void* d_out, int out_size) {
    const float* x      = (const float*)d_in[0];
    const void*  ei     = d_in[1];
    const void*  et     = d_in[2];
    const float* weight = (const float*)d_in[3];
    const float* root   = (const float*)d_in[4];
    const float* bias   = (const float*)d_in[5];
    const float* w_gate = (const float*)d_in[6];
    const float* b_gate = (const float*)d_in[7];
    float*       out    = (float*)d_out;

    detect_kernel<<<1, 32>>>((const int*)ei);
    zero_scratch_kernel<<<1024, 256>>>();
    scatter_kernel<<<NEDGE, 256>>>(x, ei, et);

    dim3 grid1(DIM / BN, (N_NODES + BM - 1) / BM);
    gemm1_kernel<<<grid1, 256>>>(x, root, weight, bias);
    gemm2_kernel<<<grid1, 256>>>(x, w_gate, b_gate, out);
}

// round 7
// speedup vs baseline: 1.0068x; 1.0068x over previous
#include <cuda_runtime.h>
#include <mma.h>
#include <math.h>
#include <stdint.h>

using namespace nvcuda;

#define N_NODES 10000
#define DIM     1024
#define NREL    8
#define NEDGE   80000
#define K1      9216
#define K2      2048

#define BM 128
#define BN 128
#define BK 32
#define NTHREADS 256
#define ALD 36                         /* A smem row stride (floats)  */
#define BLD 132                        /* B smem row stride (floats)  */
#define CLD 132                        /* epilogue staging stride     */
#define A_TILE_FLOATS (BM * ALD)       /* 4608 */
#define B_TILE_FLOATS (BK * BLD)       /* 4224 */
#define STAGE_FLOATS  (A_TILE_FLOATS + B_TILE_FLOATS)   /* 8832  */
#define SMEM_FLOATS   (2 * STAGE_FLOATS)                /* 17664 */
#define SMEM_BYTES    (SMEM_FLOATS * 4)                 /* 70656 */

/* Scratch device globals (no allocation allowed) */
__device__ float g_agg[(size_t)N_NODES * NREL * DIM];
__device__ float g_cnt[N_NODES * NREL];
__device__ float g_U[(size_t)N_NODES * DIM];
__device__ int   g_is64;

__device__ __forceinline__ float f2tf32(float f) {
    uint32_t r;
    asm("cvt.rna.tf32.f32 %0, %1;" : "=r"(r) : "f"(f));
    return __uint_as_float(r);
}

/* ================= prep kernels (verbatim from passing R2) ========= */
__global__ void detect_kernel(const int* __restrict__ ei) {
    if (threadIdx.x == 0 && blockIdx.x == 0) {
        int allzero = 1;
        for (int i = 1; i < 4096; i += 2)
            if (ei[i] != 0) { allzero = 0; break; }
        g_is64 = allzero;
    }
}

__global__ void zero_scratch_kernel() {
    size_t idx    = (size_t)blockIdx.x * blockDim.x + threadIdx.x;
    size_t stride = (size_t)gridDim.x * blockDim.x;
    float4* agg4 = reinterpret_cast<float4*>(g_agg);
    const size_t nagg4 = (size_t)N_NODES * NREL * DIM / 4;
    for (size_t i = idx; i < nagg4; i += stride)
        agg4[i] = make_float4(0.f, 0.f, 0.f, 0.f);
    float4* cnt4 = reinterpret_cast<float4*>(g_cnt);
    const size_t ncnt4 = (size_t)N_NODES * NREL / 4;
    for (size_t i = idx; i < ncnt4; i += stride)
        cnt4[i] = make_float4(0.f, 0.f, 0.f, 0.f);
}

__global__ __launch_bounds__(256)
void scatter_kernel(const float* __restrict__ x,
                    const void* __restrict__ edge_index,
                    const void* __restrict__ edge_type) {
    int e = blockIdx.x;
    int src, dst, r;
    if (g_is64) {
        const long long* ei = (const long long*)edge_index;
        const long long* et = (const long long*)edge_type;
        src = (int)ei[e]; dst = (int)ei[NEDGE + e]; r = (int)et[e];
    } else {
        const int* ei = (const int*)edge_index;
        const int* et = (const int*)edge_type;
        src = ei[e]; dst = ei[NEDGE + e]; r = et[e];
    }
    const float4* xs = reinterpret_cast<const float4*>(x + (size_t)src * DIM);
    float* out = g_agg + ((size_t)dst * NREL + r) * DIM;
    int t = threadIdx.x;
    float4 v = xs[t];
    atomicAdd(out + t * 4 + 0, v.x);
    atomicAdd(out + t * 4 + 1, v.y);
    atomicAdd(out + t * 4 + 2, v.z);
    atomicAdd(out + t * 4 + 3, v.w);
    if (t == 0)
        atomicAdd(&g_cnt[dst * NREL + r], 1.0f);
}

/* ================= WMMA tf32 GEMM ==================================
   MODE 0: U = [x | mean] @ [root ; weight] + bias     (K = 9216)
   MODE 1: z = [u | x] @ w_gate + b_gate; fused gate   (K = 2048)
   B consumed in its NATIVE row-major [k][n] layout (matrix_b row_major).
   Mean-normalization and tf32 rounding fused into the smem-store step. */
template <int MODE>
__global__ __launch_bounds__(NTHREADS)
void gemm_wmma(const float* __restrict__ x,
               const float* __restrict__ B0,      /* root   | w_gate  */
               const float* __restrict__ B1,      /* weight | unused  */
               const float* __restrict__ bvec,
               float* __restrict__ out) {
    extern __shared__ float smem[];
    const int tid = threadIdx.x;
    const int wid = tid >> 5;
    const int m0  = blockIdx.y * BM;
    const int n0  = blockIdx.x * BN;
    const int KDIM = MODE ? K2 : K1;
    const int NC   = KDIM / BK;

    float* Abuf[2] = { smem,                 smem + STAGE_FLOATS };
    float* Bbuf[2] = { smem + A_TILE_FLOATS, smem + STAGE_FLOATS + A_TILE_FLOATS };

    const int wm = (wid & 3) * 32;     /* warp rows: 2 x 16 */
    const int wn = (wid >> 2) * 64;    /* warp cols: 4 x 16 */

    wmma::fragment<wmma::accumulator, 16, 16, 8, float> acc[2][4];
#pragma unroll
    for (int mt = 0; mt < 2; mt++)
#pragma unroll
        for (int nt = 0; nt < 4; nt++)
            wmma::fill_fragment(acc[mt][nt], 0.0f);

    float4 ra[4], rb[4];

    /* global -> registers (prefetch) */
    auto ldg_tile = [&](int ci) {
        const int k0 = ci * BK;
#pragma unroll
        for (int t = 0; t < 4; t++) {
            int idx = tid + t * NTHREADS;
            int row = idx >> 3;
            int c4  = (idx & 7) << 2;
            int grow = m0 + row;
            float4 v = make_float4(0.f, 0.f, 0.f, 0.f);
            if (grow < N_NODES) {
                int k = k0 + c4;
                if (MODE == 0) {
                    if (k < DIM) {
                        v = *reinterpret_cast<const float4*>(x + (size_t)grow * DIM + k);
                    } else {
                        int kk = k - DIM;
                        int r  = kk >> 10;
                        float s = 1.0f / fmaxf(g_cnt[grow * NREL + r], 1.0f);
                        float4 a = *reinterpret_cast<const float4*>(
                            g_agg + (size_t)grow * (NREL * DIM) + kk);
                        v.x = a.x * s; v.y = a.y * s; v.z = a.z * s; v.w = a.w * s;
                    }
                } else {
                    const float* Ap = (k < DIM)
                        ? (g_U + (size_t)grow * DIM + k)
                        : (x + (size_t)grow * DIM + (k - DIM));
                    v = *reinterpret_cast<const float4*>(Ap);
                }
            }
            ra[t] = v;
        }
#pragma unroll
        for (int t = 0; t < 4; t++) {
            int idx = tid + t * NTHREADS;
            int kr  = idx >> 5;
            int c4  = (idx & 31) << 2;
            int k   = k0 + kr;
            const float* src;
            if (MODE == 0)
                src = (k < DIM) ? (B0 + (size_t)k * DIM + n0 + c4)
                                : (B1 + (size_t)(k - DIM) * DIM + n0 + c4);
            else
                src = B0 + (size_t)k * DIM + n0 + c4;
            rb[t] = *reinterpret_cast<const float4*>(src);
        }
    };

    /* registers -> smem with tf32 rounding */
    auto st_tile = [&](int s) {
#pragma unroll
        for (int t = 0; t < 4; t++) {
            int idx = tid + t * NTHREADS;
            int row = idx >> 3;
            int c4  = (idx & 7) << 2;
            float* p = Abuf[s] + row * ALD + c4;
            p[0] = f2tf32(ra[t].x); p[1] = f2tf32(ra[t].y);
            p[2] = f2tf32(ra[t].z); p[3] = f2tf32(ra[t].w);
        }
#pragma unroll
        for (int t = 0; t < 4; t++) {
            int idx = tid + t * NTHREADS;
            int kr  = idx >> 5;
            int c4  = (idx & 31) << 2;
            float* p = Bbuf[s] + kr * BLD + c4;
            p[0] = f2tf32(rb[t].x); p[1] = f2tf32(rb[t].y);
            p[2] = f2tf32(rb[t].z); p[3] = f2tf32(rb[t].w);
        }
    };

    ldg_tile(0);

    for (int ci = 0; ci < NC; ci++) {
        const int s = ci & 1;
        st_tile(s);
        __syncthreads();
        if (ci + 1 < NC) ldg_tile(ci + 1);   /* LDGs retire under compute */

#pragma unroll
        for (int kk = 0; kk < 4; kk++) {
            wmma::fragment<wmma::matrix_a, 16, 16, 8,
                           wmma::precision::tf32, wmma::row_major> fa[2];
            wmma::fragment<wmma::matrix_b, 16, 16, 8,
                           wmma::precision::tf32, wmma::row_major> fb[4];
#pragma unroll
            for (int mt = 0; mt < 2; mt++)
                wmma::load_matrix_sync(fa[mt], Abuf[s] + (wm + mt * 16) * ALD + kk * 8, ALD);
#pragma unroll
            for (int nt = 0; nt < 4; nt++)
                wmma::load_matrix_sync(fb[nt], Bbuf[s] + (kk * 8) * BLD + wn + nt * 16, BLD);
#pragma unroll
            for (int mt = 0; mt < 2; mt++)
#pragma unroll
                for (int nt = 0; nt < 4; nt++)
                    wmma::mma_sync(acc[mt][nt], fa[mt], fb[nt], acc[mt][nt]);
        }
        /* one sync per iteration: the collective sync at iter ci+1 fences
           iter ci's readers of buffer s from iter ci+2's writers of s.   */
    }

    /* ---- epilogue: stage accumulators in smem, then elementwise ---- */
    __syncthreads();
    float* stg = smem;                       /* 128 x CLD, reuses tiles */
#pragma unroll
    for (int mt = 0; mt < 2; mt++)
#pragma unroll
        for (int nt = 0; nt < 4; nt++)
            wmma::store_matrix_sync(stg + (wm + mt * 16) * CLD + wn + nt * 16,
                                    acc[mt][nt], CLD, wmma::mem_row_major);
    __syncthreads();

#pragma unroll
    for (int t = 0; t < 16; t++) {
        int idx = tid + t * NTHREADS;        /* 4096 float4 = 128x128 */
        int row = idx >> 5;
        int c4  = (idx & 31) << 2;
        int grow = m0 + row;
        if (grow >= N_NODES) continue;
        int gc = n0 + c4;
        const float* sp = stg + row * CLD + c4;
        float4 bv = *reinterpret_cast<const float4*>(bvec + gc);
        float z0 = sp[0] + bv.x, z1 = sp[1] + bv.y;
        float z2 = sp[2] + bv.z, z3 = sp[3] + bv.w;
        size_t o = (size_t)grow * DIM + gc;
        if (MODE == 0) {
            *reinterpret_cast<float4*>(g_U + o) = make_float4(z0, z1, z2, z3);
        } else {
            float4 u4 = *reinterpret_cast<const float4*>(g_U + o);
            float4 x4 = *reinterpret_cast<const float4*>(x + o);
            float h0 = tanhf(u4.x) * z0 + x4.x * (1.0f - z0);
            float h1 = tanhf(u4.y) * z1 + x4.y * (1.0f - z1);
            float h2 = tanhf(u4.z) * z2 + x4.z * (1.0f - z2);
            float h3 = tanhf(u4.w) * z3 + x4.w * (1.0f - z3);
            *reinterpret_cast<float4*>(out + o) = make_float4(h0, h1, h2, h3);
        }
    }
}

/* ================= launch ================= */
extern "C" void kernel_launch(void* const* d_in, const int* in_sizes, int n_in,
                              void* d_out, int out_size) {
    const float* x      = (const float*)d_in[0];
    const void*  ei     = d_in[1];
    const void*  et     = d_in[2];
    const float* weight = (const float*)d_in[3];
    const float* root   = (const float*)d_in[4];
    const float* bias   = (const float*)d_in[5];
    const float* w_gate = (const float*)d_in[6];
    const float* b_gate = (const float*)d_in[7];
    float*       out    = (float*)d_out;

    cudaFuncSetAttribute(gemm_wmma<0>, cudaFuncAttributeMaxDynamicSharedMemorySize, SMEM_BYTES);
    cudaFuncSetAttribute(gemm_wmma<1>, cudaFuncAttributeMaxDynamicSharedMemorySize, SMEM_BYTES);

    detect_kernel<<<1, 32>>>((const int*)ei);
    zero_scratch_kernel<<<1024, 256>>>();
    scatter_kernel<<<NEDGE, 256>>>(x, ei, et);

    dim3 grid(DIM / BN, (N_NODES + BM - 1) / BM);   /* 8 x 79 */
    gemm_wmma<0><<<grid, NTHREADS, SMEM_BYTES>>>(x, root, weight, bias, nullptr);
    gemm_wmma<1><<<grid, NTHREADS, SMEM_BYTES>>>(x, w_gate, nullptr, b_gate, out);
}

// round 9
// speedup vs baseline: 1.4320x; 1.4223x over previous
#include <cuda_runtime.h>
#include <mma.h>
#include <math.h>
#include <stdint.h>

using namespace nvcuda;

#define N_NODES 10000
#define DIM     1024
#define NREL    8
#define NEDGE   80000
#define K1      9216
#define K2      2048

#define BM 128
#define BN 128
#define BK 64
#define NTHREADS 256
#define ALD 68                          /* A smem row stride (floats) */
#define BLD 132                         /* B smem row stride (floats) */
#define CLD 132                         /* epilogue staging stride    */
#define A_TILE_FLOATS (BM * ALD)        /* 8704  */
#define B_TILE_FLOATS (BK * BLD)        /* 8448  */
#define STAGE_FLOATS  (A_TILE_FLOATS + B_TILE_FLOATS)  /* 17152 */
#define SMEM_BYTES    (STAGE_FLOATS * 4)               /* 68608 (>= 128*CLD*4) */

/* Scratch device globals (no allocation allowed) */
__device__ float g_agg[(size_t)N_NODES * NREL * DIM];
__device__ float g_cnt[N_NODES * NREL];
__device__ float g_U[(size_t)N_NODES * DIM];
__device__ int   g_is64;

__device__ __forceinline__ float f2tf32(float f) {
    uint32_t r;
    asm("cvt.rna.tf32.f32 %0, %1;" : "=r"(r) : "f"(f));
    return __uint_as_float(r);
}

/* ================= prep kernels (verbatim from passing R2/R7) ====== */
__global__ void detect_kernel(const int* __restrict__ ei) {
    if (threadIdx.x == 0 && blockIdx.x == 0) {
        int allzero = 1;
        for (int i = 1; i < 4096; i += 2)
            if (ei[i] != 0) { allzero = 0; break; }
        g_is64 = allzero;
    }
}

__global__ void zero_scratch_kernel() {
    size_t idx    = (size_t)blockIdx.x * blockDim.x + threadIdx.x;
    size_t stride = (size_t)gridDim.x * blockDim.x;
    float4* agg4 = reinterpret_cast<float4*>(g_agg);
    const size_t nagg4 = (size_t)N_NODES * NREL * DIM / 4;
    for (size_t i = idx; i < nagg4; i += stride)
        agg4[i] = make_float4(0.f, 0.f, 0.f, 0.f);
    float4* cnt4 = reinterpret_cast<float4*>(g_cnt);
    const size_t ncnt4 = (size_t)N_NODES * NREL / 4;
    for (size_t i = idx; i < ncnt4; i += stride)
        cnt4[i] = make_float4(0.f, 0.f, 0.f, 0.f);
}

__global__ __launch_bounds__(256)
void scatter_kernel(const float* __restrict__ x,
                    const void* __restrict__ edge_index,
                    const void* __restrict__ edge_type) {
    int e = blockIdx.x;
    int src, dst, r;
    if (g_is64) {
        const long long* ei = (const long long*)edge_index;
        const long long* et = (const long long*)edge_type;
        src = (int)ei[e]; dst = (int)ei[NEDGE + e]; r = (int)et[e];
    } else {
        const int* ei = (const int*)edge_index;
        const int* et = (const int*)edge_type;
        src = ei[e]; dst = ei[NEDGE + e]; r = et[e];
    }
    const float4* xs = reinterpret_cast<const float4*>(x + (size_t)src * DIM);
    float* out = g_agg + ((size_t)dst * NREL + r) * DIM;
    int t = threadIdx.x;
    float4 v = xs[t];
    atomicAdd(out + t * 4 + 0, v.x);
    atomicAdd(out + t * 4 + 1, v.y);
    atomicAdd(out + t * 4 + 2, v.z);
    atomicAdd(out + t * 4 + 3, v.w);
    if (t == 0)
        atomicAdd(&g_cnt[dst * NREL + r], 1.0f);
}

/* ================= WMMA tf32 GEMM (R7 math, phase-overlap via occ=2)
   MODE 0: U = [x | mean] @ [root ; weight] + bias     (K = 9216)
   MODE 1: z = [u | x] @ w_gate + b_gate; fused gate   (K = 2048)      */
template <int MODE>
__global__ __launch_bounds__(NTHREADS, 2)
void gemm_wmma(const float* __restrict__ x,
               const float* __restrict__ B0,      /* root   | w_gate */
               const float* __restrict__ B1,      /* weight | unused */
               const float* __restrict__ bvec,
               float* __restrict__ out) {
    extern __shared__ float smem[];
    const int tid = threadIdx.x;
    const int wid = tid >> 5;
    const int m0  = blockIdx.y * BM;
    const int n0  = blockIdx.x * BN;
    const int KDIM = MODE ? K2 : K1;
    const int NC   = KDIM / BK;

    float* Abuf = smem;
    float* Bbuf = smem + A_TILE_FLOATS;

    const int wm = (wid & 3) * 32;     /* warp rows: 2 x 16 */
    const int wn = (wid >> 2) * 64;    /* warp cols: 4 x 16 */

    wmma::fragment<wmma::accumulator, 16, 16, 8, float> acc[2][4];
#pragma unroll
    for (int mt = 0; mt < 2; mt++)
#pragma unroll
        for (int nt = 0; nt < 4; nt++)
            wmma::fill_fragment(acc[mt][nt], 0.0f);

    for (int ci = 0; ci < NC; ci++) {
        const int k0 = ci * BK;
        __syncthreads();               /* prev readers done before overwrite */

        /* ---- load phase: A 128x64, B 64x128, tf32-round at STS ---- */
#pragma unroll
        for (int t = 0; t < 8; t++) {
            int idx = tid + t * NTHREADS;
            int row = idx >> 4;                  /* 16 float4 per A row */
            int c4  = (idx & 15) << 2;
            int grow = m0 + row;
            float4 v = make_float4(0.f, 0.f, 0.f, 0.f);
            if (grow < N_NODES) {
                int k = k0 + c4;
                if (MODE == 0) {
                    if (k < DIM) {
                        v = *reinterpret_cast<const float4*>(x + (size_t)grow * DIM + k);
                    } else {
                        int kk = k - DIM;
                        int r  = kk >> 10;
                        float s = 1.0f / fmaxf(g_cnt[grow * NREL + r], 1.0f);
                        float4 a = *reinterpret_cast<const float4*>(
                            g_agg + (size_t)grow * (NREL * DIM) + kk);
                        v.x = a.x * s; v.y = a.y * s; v.z = a.z * s; v.w = a.w * s;
                    }
                } else {
                    const float* Ap = (k < DIM)
                        ? (g_U + (size_t)grow * DIM + k)
                        : (x + (size_t)grow * DIM + (k - DIM));
                    v = *reinterpret_cast<const float4*>(Ap);
                }
            }
            float* p = Abuf + row * ALD + c4;
            p[0] = f2tf32(v.x); p[1] = f2tf32(v.y);
            p[2] = f2tf32(v.z); p[3] = f2tf32(v.w);
        }
#pragma unroll
        for (int t = 0; t < 8; t++) {
            int idx = tid + t * NTHREADS;
            int kr  = idx >> 5;                  /* 0..63 */
            int c4  = (idx & 31) << 2;
            int k   = k0 + kr;
            const float* src;
            if (MODE == 0)
                src = (k < DIM) ? (B0 + (size_t)k * DIM + n0 + c4)
                                : (B1 + (size_t)(k - DIM) * DIM + n0 + c4);
            else
                src = B0 + (size_t)k * DIM + n0 + c4;
            float4 v = *reinterpret_cast<const float4*>(src);
            float* p = Bbuf + kr * BLD + c4;
            p[0] = f2tf32(v.x); p[1] = f2tf32(v.y);
            p[2] = f2tf32(v.z); p[3] = f2tf32(v.w);
        }
        __syncthreads();

        /* ---- MMA phase ---- */
#pragma unroll
        for (int kk = 0; kk < 8; kk++) {
            wmma::fragment<wmma::matrix_b, 16, 16, 8,
                           wmma::precision::tf32, wmma::row_major> fb[4];
#pragma unroll
            for (int nt = 0; nt < 4; nt++)
                wmma::load_matrix_sync(fb[nt], Bbuf + (kk * 8) * BLD + wn + nt * 16, BLD);
#pragma unroll
            for (int mt = 0; mt < 2; mt++) {
                wmma::fragment<wmma::matrix_a, 16, 16, 8,
                               wmma::precision::tf32, wmma::row_major> fa;
                wmma::load_matrix_sync(fa, Abuf + (wm + mt * 16) * ALD + kk * 8, ALD);
#pragma unroll
                for (int nt = 0; nt < 4; nt++)
                    wmma::mma_sync(acc[mt][nt], fa, fb[nt], acc[mt][nt]);
            }
        }
    }

    /* ---- epilogue: stage accumulators in smem, then elementwise ---- */
    __syncthreads();
    float* stg = smem;                       /* 128 x CLD fits in SMEM_BYTES */
#pragma unroll
    for (int mt = 0; mt < 2; mt++)
#pragma unroll
        for (int nt = 0; nt < 4; nt++)
            wmma::store_matrix_sync(stg + (wm + mt * 16) * CLD + wn + nt * 16,
                                    acc[mt][nt], CLD, wmma::mem_row_major);
    __syncthreads();

#pragma unroll
    for (int t = 0; t < 16; t++) {
        int idx = tid + t * NTHREADS;        /* 4096 float4 = 128x128 */
        int row = idx >> 5;
        int c4  = (idx & 31) << 2;
        int grow = m0 + row;
        if (grow >= N_NODES) continue;
        int gc = n0 + c4;
        const float* sp = stg + row * CLD + c4;
        float4 bv = *reinterpret_cast<const float4*>(bvec + gc);
        float z0 = sp[0] + bv.x, z1 = sp[1] + bv.y;
        float z2 = sp[2] + bv.z, z3 = sp[3] + bv.w;
        size_t o = (size_t)grow * DIM + gc;
        if (MODE == 0) {
            *reinterpret_cast<float4*>(g_U + o) = make_float4(z0, z1, z2, z3);
        } else {
            float4 u4 = *reinterpret_cast<const float4*>(g_U + o);
            float4 x4 = *reinterpret_cast<const float4*>(x + o);
            float h0 = tanhf(u4.x) * z0 + x4.x * (1.0f - z0);
            float h1 = tanhf(u4.y) * z1 + x4.y * (1.0f - z1);
            float h2 = tanhf(u4.z) * z2 + x4.z * (1.0f - z2);
            float h3 = tanhf(u4.w) * z3 + x4.w * (1.0f - z3);
            *reinterpret_cast<float4*>(out + o) = make_float4(h0, h1, h2, h3);
        }
    }
}

/* ================= launch ================= */
extern "C" void kernel_launch(void* const* d_in, const int* in_sizes, int n_in,
                              void* d_out, int out_size) {
    const float* x      = (const float*)d_in[0];
    const void*  ei     = d_in[1];
    const void*  et     = d_in[2];
    const float* weight = (const float*)d_in[3];
    const float* root   = (const float*)d_in[4];
    const float* bias   = (const float*)d_in[5];
    const float* w_gate = (const float*)d_in[6];
    const float* b_gate = (const float*)d_in[7];
    float*       out    = (float*)d_out;

    cudaFuncSetAttribute(gemm_wmma<0>, cudaFuncAttributeMaxDynamicSharedMemorySize, SMEM_BYTES);
    cudaFuncSetAttribute(gemm_wmma<1>, cudaFuncAttributeMaxDynamicSharedMemorySize, SMEM_BYTES);

    detect_kernel<<<1, 32>>>((const int*)ei);
    zero_scratch_kernel<<<1024, 256>>>();
    scatter_kernel<<<NEDGE, 256>>>(x, ei, et);

    dim3 grid(DIM / BN, (N_NODES + BM - 1) / BM);   /* 8 x 79 */
    gemm_wmma<0><<<grid, NTHREADS, SMEM_BYTES>>>(x, root, weight, bias, nullptr);
    gemm_wmma<1><<<grid, NTHREADS, SMEM_BYTES>>>(x, w_gate, nullptr, b_gate, out);
}